// round 1
// baseline (speedup 1.0000x reference)
#include <cuda_runtime.h>

// EquivariantLayerNorm: out = (covar + EPS*I)^{-1/2} @ (x - mean) * weight
// covar = xc @ xc^T / D + EPS*diag(1,2,3),  x: (N, 3, 256) fp32.
//
// Key identity: V diag(1/sqrt(s+eps)) V^T of SVD(covar) == (covar + eps I)^{-1/2}
// (covar symmetric PSD). Computed via Newton-Schulz iteration on the 3x3.
//
// Mapping: 256-thread block = 4 samples. 64 threads/sample, each owns 4
// consecutive columns (float4). One 9-quantity reduction (3 row sums + 6
// raw second moments), leader thread per sample runs 8 NS iterations,
// broadcast S + means through smem, fused epilogue.

#define NS_ITERS 8

__global__ void __launch_bounds__(256) eqln_kernel(
    const float* __restrict__ in,
    const float* __restrict__ weight,
    float* __restrict__ out,
    int nSamples)
{
    __shared__ float warp_part[8][9];   // per-warp partial sums
    __shared__ float grp_res[4][9];     // per-sample: S00,S01,S02,S11,S12,S22,m0,m1,m2

    const int tid  = threadIdx.x;
    const int g    = tid >> 6;          // sample group within block, 0..3
    const int gt   = tid & 63;          // thread within group (column/4)
    const int warp = tid >> 5;          // 0..7
    const int lane = tid & 31;

    long sample = (long)blockIdx.x * 4 + g;
    const bool valid = (sample < (long)nSamples);
    long ls = valid ? sample : (long)nSamples - 1;   // clamp for safe load

    const float4* __restrict__ xin = (const float4*)(in + ls * 768);
    float4 x0 = xin[      gt];
    float4 x1 = xin[ 64 + gt];
    float4 x2 = xin[128 + gt];

    // 9 partial sums: row sums + unique second moments
    float s[9];
    s[0] = (x0.x + x0.y) + (x0.z + x0.w);
    s[1] = (x1.x + x1.y) + (x1.z + x1.w);
    s[2] = (x2.x + x2.y) + (x2.z + x2.w);
    s[3] = x0.x*x0.x + x0.y*x0.y + x0.z*x0.z + x0.w*x0.w;
    s[4] = x0.x*x1.x + x0.y*x1.y + x0.z*x1.z + x0.w*x1.w;
    s[5] = x0.x*x2.x + x0.y*x2.y + x0.z*x2.z + x0.w*x2.w;
    s[6] = x1.x*x1.x + x1.y*x1.y + x1.z*x1.z + x1.w*x1.w;
    s[7] = x1.x*x2.x + x1.y*x2.y + x1.z*x2.z + x1.w*x2.w;
    s[8] = x2.x*x2.x + x2.y*x2.y + x2.z*x2.z + x2.w*x2.w;

    #pragma unroll
    for (int q = 0; q < 9; q++) {
        #pragma unroll
        for (int o = 16; o > 0; o >>= 1)
            s[q] += __shfl_xor_sync(0xffffffffu, s[q], o);
    }
    if (lane == 0) {
        #pragma unroll
        for (int q = 0; q < 9; q++) warp_part[warp][q] = s[q];
    }
    __syncthreads();

    if (gt == 0) {
        // combine the two warps of this group
        float t[9];
        #pragma unroll
        for (int q = 0; q < 9; q++)
            t[q] = warp_part[2*g][q] + warp_part[2*g + 1][q];

        const float invD = 1.0f / 256.0f;
        float m0 = t[0] * invD, m1 = t[1] * invD, m2 = t[2] * invD;

        // A = covar + EPS*diag(1,2,3) + EPS*I  (the +EPS*I comes from 1/sqrt(s+eps))
        float a00 = t[3]*invD - m0*m0 + 2.0e-3f;
        float a01 = t[4]*invD - m0*m1;
        float a02 = t[5]*invD - m0*m2;
        float a11 = t[6]*invD - m1*m1 + 3.0e-3f;
        float a12 = t[7]*invD - m1*m2;
        float a22 = t[8]*invD - m2*m2 + 4.0e-3f;

        // Newton-Schulz for A^{-1/2}: B = A/c, X=I, X <- 0.5*X*(3I - B X^2)
        float c  = (a00 + a11 + a22) * (1.0f / 3.0f);
        float ic = 1.0f / c;
        float b00 = a00*ic, b01 = a01*ic, b02 = a02*ic;
        float b11 = a11*ic, b12 = a12*ic, b22 = a22*ic;

        float x00 = 1.0f, x01 = 0.0f, x02 = 0.0f;
        float x11 = 1.0f, x12 = 0.0f, x22 = 1.0f;

        #pragma unroll
        for (int it = 0; it < NS_ITERS; it++) {
            // T = X*X (symmetric)
            float t00 = x00*x00 + x01*x01 + x02*x02;
            float t01 = x00*x01 + x01*x11 + x02*x12;
            float t02 = x00*x02 + x01*x12 + x02*x22;
            float t11 = x01*x01 + x11*x11 + x12*x12;
            float t12 = x01*x02 + x11*x12 + x12*x22;
            float t22 = x02*x02 + x12*x12 + x22*x22;
            // W = B*T (symmetric in exact arithmetic; take upper triangle)
            float w00 = b00*t00 + b01*t01 + b02*t02;
            float w01 = b00*t01 + b01*t11 + b02*t12;
            float w02 = b00*t02 + b01*t12 + b02*t22;
            float w11 = b01*t01 + b11*t11 + b12*t12;
            float w12 = b01*t02 + b11*t12 + b12*t22;
            float w22 = b02*t02 + b12*t12 + b22*t22;
            // M = 3I - W
            float q00 = 3.0f - w00, q01 = -w01, q02 = -w02;
            float q11 = 3.0f - w11, q12 = -w12, q22 = 3.0f - w22;
            // X = 0.5 * X * M
            float n00 = x00*q00 + x01*q01 + x02*q02;
            float n01 = x00*q01 + x01*q11 + x02*q12;
            float n02 = x00*q02 + x01*q12 + x02*q22;
            float n11 = x01*q01 + x11*q11 + x12*q12;
            float n12 = x01*q02 + x11*q12 + x12*q22;
            float n22 = x02*q02 + x12*q12 + x22*q22;
            x00 = 0.5f*n00; x01 = 0.5f*n01; x02 = 0.5f*n02;
            x11 = 0.5f*n11; x12 = 0.5f*n12; x22 = 0.5f*n22;
        }

        float isc = rsqrtf(c);   // A^{-1/2} = X / sqrt(c)
        grp_res[g][0] = x00 * isc;
        grp_res[g][1] = x01 * isc;
        grp_res[g][2] = x02 * isc;
        grp_res[g][3] = x11 * isc;
        grp_res[g][4] = x12 * isc;
        grp_res[g][5] = x22 * isc;
        grp_res[g][6] = m0;
        grp_res[g][7] = m1;
        grp_res[g][8] = m2;
    }
    __syncthreads();

    float S00 = grp_res[g][0], S01 = grp_res[g][1], S02 = grp_res[g][2];
    float S11 = grp_res[g][3], S12 = grp_res[g][4], S22 = grp_res[g][5];
    float m0  = grp_res[g][6], m1  = grp_res[g][7], m2  = grp_res[g][8];

    float4 w4 = ((const float4*)weight)[gt];

    float4 o0, o1, o2;
    {
        float c0, c1, c2;
        c0 = x0.x - m0; c1 = x1.x - m1; c2 = x2.x - m2;
        o0.x = (S00*c0 + S01*c1 + S02*c2) * w4.x;
        o1.x = (S01*c0 + S11*c1 + S12*c2) * w4.x;
        o2.x = (S02*c0 + S12*c1 + S22*c2) * w4.x;
        c0 = x0.y - m0; c1 = x1.y - m1; c2 = x2.y - m2;
        o0.y = (S00*c0 + S01*c1 + S02*c2) * w4.y;
        o1.y = (S01*c0 + S11*c1 + S12*c2) * w4.y;
        o2.y = (S02*c0 + S12*c1 + S22*c2) * w4.y;
        c0 = x0.z - m0; c1 = x1.z - m1; c2 = x2.z - m2;
        o0.z = (S00*c0 + S01*c1 + S02*c2) * w4.z;
        o1.z = (S01*c0 + S11*c1 + S12*c2) * w4.z;
        o2.z = (S02*c0 + S12*c1 + S22*c2) * w4.z;
        c0 = x0.w - m0; c1 = x1.w - m1; c2 = x2.w - m2;
        o0.w = (S00*c0 + S01*c1 + S02*c2) * w4.w;
        o1.w = (S01*c0 + S11*c1 + S12*c2) * w4.w;
        o2.w = (S02*c0 + S12*c1 + S22*c2) * w4.w;
    }

    if (valid) {
        float4* __restrict__ xout = (float4*)(out + sample * 768);
        xout[      gt] = o0;
        xout[ 64 + gt] = o1;
        xout[128 + gt] = o2;
    }
}

extern "C" void kernel_launch(void* const* d_in, const int* in_sizes, int n_in,
                              void* d_out, int out_size)
{
    const float* in = (const float*)d_in[0];
    const float* w  = (const float*)d_in[1];
    float* out      = (float*)d_out;

    int nSamples = in_sizes[0] / 768;        // N*3*256 elements -> N samples
    int grid = (nSamples + 3) / 4;
    eqln_kernel<<<grid, 256>>>(in, w, out, nSamples);
}

// round 2
// speedup vs baseline: 1.0642x; 1.0642x over previous
#include <cuda_runtime.h>

// EquivariantLayerNorm: out = (covar + EPS*I)^{-1/2} @ (x - mean) * weight
// covar = xc @ xc^T / D + EPS*diag(1,2,3),  x: (N, 3, 256) fp32.
//
// (V diag(1/sqrt(s+eps)) V^T over SVD(covar)) == (covar + eps I)^{-1/2}, computed
// via Newton-Schulz on the 3x3.
//
// R2 layout: 256-thread block = 8 samples, one WARP per sample.
//  - Each lane loads 2 float4 per row (6 independent LDG.128, MLP=6).
//  - 9-quantity butterfly reduction within the warp (no smem/syncthreads pass).
//  - Newton-Schulz is LANE-PARALLEL: warp 0 lanes 0..7 each solve one sample's
//    3x3 scalarly (8x fewer warp-instructions than leader-per-warp).
//  - Epilogue uses bias b = -S*m so each column is 3 FMA + 1 mul per row.

#define NS_ITERS 8

__device__ __forceinline__ float hsum8(float4 a, float4 b) {
    return ((a.x + a.y) + (a.z + a.w)) + ((b.x + b.y) + (b.z + b.w));
}
__device__ __forceinline__ float dot8(float4 a0, float4 a1, float4 b0, float4 b1) {
    float r = a0.x * b0.x;
    r = fmaf(a0.y, b0.y, r);
    r = fmaf(a0.z, b0.z, r);
    r = fmaf(a0.w, b0.w, r);
    r = fmaf(a1.x, b1.x, r);
    r = fmaf(a1.y, b1.y, r);
    r = fmaf(a1.z, b1.z, r);
    r = fmaf(a1.w, b1.w, r);
    return r;
}

__global__ void __launch_bounds__(256) eqln_kernel(
    const float* __restrict__ in,
    const float* __restrict__ weight,
    float* __restrict__ out,
    int nSamples)
{
    __shared__ float ssum[8][9];   // per-sample raw sums
    __shared__ float sres[8][9];   // per-sample S00,S01,S02,S11,S12,S22,b0,b1,b2

    const int warp = threadIdx.x >> 5;   // sample within block, 0..7
    const int lane = threadIdx.x & 31;

    long sample = (long)blockIdx.x * 8 + warp;
    const bool valid = (sample < (long)nSamples);
    long ls = valid ? sample : (long)nSamples - 1;   // clamp for safe load

    const float4* __restrict__ xin = (const float4*)(in + ls * 768);
    // row r: float4 index lane and lane+32 (coalesced)
    float4 r0a = xin[       lane];
    float4 r0b = xin[ 32 +  lane];
    float4 r1a = xin[ 64 +  lane];
    float4 r1b = xin[ 96 +  lane];
    float4 r2a = xin[128 +  lane];
    float4 r2b = xin[160 +  lane];

    // 9 partial sums: row sums + unique raw second moments
    float s[9];
    s[0] = hsum8(r0a, r0b);
    s[1] = hsum8(r1a, r1b);
    s[2] = hsum8(r2a, r2b);
    s[3] = dot8(r0a, r0b, r0a, r0b);
    s[4] = dot8(r0a, r0b, r1a, r1b);
    s[5] = dot8(r0a, r0b, r2a, r2b);
    s[6] = dot8(r1a, r1b, r1a, r1b);
    s[7] = dot8(r1a, r1b, r2a, r2b);
    s[8] = dot8(r2a, r2b, r2a, r2b);

    #pragma unroll
    for (int q = 0; q < 9; q++) {
        #pragma unroll
        for (int o = 16; o > 0; o >>= 1)
            s[q] += __shfl_xor_sync(0xffffffffu, s[q], o);
    }
    if (lane == 0) {
        #pragma unroll
        for (int q = 0; q < 9; q++) ssum[warp][q] = s[q];
    }
    __syncthreads();

    // Lane-parallel Newton-Schulz: warp 0, lane k solves sample k of this block.
    if (warp == 0 && lane < 8) {
        float t[9];
        #pragma unroll
        for (int q = 0; q < 9; q++) t[q] = ssum[lane][q];

        const float invD = 1.0f / 256.0f;
        float m0 = t[0] * invD, m1 = t[1] * invD, m2 = t[2] * invD;

        // A = covar + EPS*diag(1,2,3) + EPS*I   (the +EPS*I from 1/sqrt(s+eps))
        float a00 = fmaf(t[3], invD, -m0 * m0) + 2.0e-3f;
        float a01 = fmaf(t[4], invD, -m0 * m1);
        float a02 = fmaf(t[5], invD, -m0 * m2);
        float a11 = fmaf(t[6], invD, -m1 * m1) + 3.0e-3f;
        float a12 = fmaf(t[7], invD, -m1 * m2);
        float a22 = fmaf(t[8], invD, -m2 * m2) + 4.0e-3f;

        // Newton-Schulz for A^{-1/2}: B = A/c, X=I, X <- 0.5*X*(3I - B X^2)
        float c  = (a00 + a11 + a22) * (1.0f / 3.0f);
        float ic = 1.0f / c;
        float b00 = a00 * ic, b01 = a01 * ic, b02 = a02 * ic;
        float b11 = a11 * ic, b12 = a12 * ic, b22 = a22 * ic;

        float x00 = 1.0f, x01 = 0.0f, x02 = 0.0f;
        float x11 = 1.0f, x12 = 0.0f, x22 = 1.0f;

        #pragma unroll
        for (int it = 0; it < NS_ITERS; it++) {
            float t00 = x00*x00 + x01*x01 + x02*x02;
            float t01 = x00*x01 + x01*x11 + x02*x12;
            float t02 = x00*x02 + x01*x12 + x02*x22;
            float t11 = x01*x01 + x11*x11 + x12*x12;
            float t12 = x01*x02 + x11*x12 + x12*x22;
            float t22 = x02*x02 + x12*x12 + x22*x22;

            float w00 = b00*t00 + b01*t01 + b02*t02;
            float w01 = b00*t01 + b01*t11 + b02*t12;
            float w02 = b00*t02 + b01*t12 + b02*t22;
            float w11 = b01*t01 + b11*t11 + b12*t12;
            float w12 = b01*t02 + b11*t12 + b12*t22;
            float w22 = b02*t02 + b12*t12 + b22*t22;

            float q00 = 3.0f - w00, q01 = -w01, q02 = -w02;
            float q11 = 3.0f - w11, q12 = -w12, q22 = 3.0f - w22;

            float n00 = x00*q00 + x01*q01 + x02*q02;
            float n01 = x00*q01 + x01*q11 + x02*q12;
            float n02 = x00*q02 + x01*q12 + x02*q22;
            float n11 = x01*q01 + x11*q11 + x12*q12;
            float n12 = x01*q02 + x11*q12 + x12*q22;
            float n22 = x02*q02 + x12*q12 + x22*q22;

            x00 = 0.5f*n00; x01 = 0.5f*n01; x02 = 0.5f*n02;
            x11 = 0.5f*n11; x12 = 0.5f*n12; x22 = 0.5f*n22;
        }

        float isc = rsqrtf(c);   // A^{-1/2} = X / sqrt(c)
        float S00 = x00 * isc, S01 = x01 * isc, S02 = x02 * isc;
        float S11 = x11 * isc, S12 = x12 * isc, S22 = x22 * isc;

        sres[lane][0] = S00;
        sres[lane][1] = S01;
        sres[lane][2] = S02;
        sres[lane][3] = S11;
        sres[lane][4] = S12;
        sres[lane][5] = S22;
        // bias b = -S*m (folds mean subtraction into the transform)
        sres[lane][6] = -(S00*m0 + S01*m1 + S02*m2);
        sres[lane][7] = -(S01*m0 + S11*m1 + S12*m2);
        sres[lane][8] = -(S02*m0 + S12*m1 + S22*m2);
    }
    __syncthreads();

    const float S00 = sres[warp][0], S01 = sres[warp][1], S02 = sres[warp][2];
    const float S11 = sres[warp][3], S12 = sres[warp][4], S22 = sres[warp][5];
    const float bb0 = sres[warp][6], bb1 = sres[warp][7], bb2 = sres[warp][8];

    const float4* __restrict__ w4p = (const float4*)weight;
    float4 wa = w4p[lane];
    float4 wb = w4p[32 + lane];

    float4 o0a, o1a, o2a, o0b, o1b, o2b;
    #define COLOUT(O0, O1, O2, X0, X1, X2, W)                                  \
        O0 = (fmaf(S00, X0, fmaf(S01, X1, fmaf(S02, X2, bb0)))) * W;           \
        O1 = (fmaf(S01, X0, fmaf(S11, X1, fmaf(S12, X2, bb1)))) * W;           \
        O2 = (fmaf(S02, X0, fmaf(S12, X1, fmaf(S22, X2, bb2)))) * W;

    COLOUT(o0a.x, o1a.x, o2a.x, r0a.x, r1a.x, r2a.x, wa.x)
    COLOUT(o0a.y, o1a.y, o2a.y, r0a.y, r1a.y, r2a.y, wa.y)
    COLOUT(o0a.z, o1a.z, o2a.z, r0a.z, r1a.z, r2a.z, wa.z)
    COLOUT(o0a.w, o1a.w, o2a.w, r0a.w, r1a.w, r2a.w, wa.w)
    COLOUT(o0b.x, o1b.x, o2b.x, r0b.x, r1b.x, r2b.x, wb.x)
    COLOUT(o0b.y, o1b.y, o2b.y, r0b.y, r1b.y, r2b.y, wb.y)
    COLOUT(o0b.z, o1b.z, o2b.z, r0b.z, r1b.z, r2b.z, wb.z)
    COLOUT(o0b.w, o1b.w, o2b.w, r0b.w, r1b.w, r2b.w, wb.w)
    #undef COLOUT

    if (valid) {
        float4* __restrict__ xout = (float4*)(out + sample * 768);
        xout[       lane] = o0a;
        xout[ 32 +  lane] = o0b;
        xout[ 64 +  lane] = o1a;
        xout[ 96 +  lane] = o1b;
        xout[128 +  lane] = o2a;
        xout[160 +  lane] = o2b;
    }
}

extern "C" void kernel_launch(void* const* d_in, const int* in_sizes, int n_in,
                              void* d_out, int out_size)
{
    const float* in = (const float*)d_in[0];
    const float* w  = (const float*)d_in[1];
    float* out      = (float*)d_out;

    int nSamples = in_sizes[0] / 768;        // N*3*256 elements -> N samples
    int grid = (nSamples + 7) / 8;
    eqln_kernel<<<grid, 256>>>(in, w, out, nSamples);
}

// round 3
// speedup vs baseline: 1.3313x; 1.2509x over previous
#include <cuda_runtime.h>
#include <cstdint>

// EquivariantLayerNorm: out = (covar + EPS*I)^{-1/2} @ (x - mean) * weight
// covar = xc @ xc^T / D + EPS*diag(1,2,3),  x: (N, 3, 256) fp32.
//
// (V diag(1/sqrt(s+eps)) V^T over SVD(covar)) == (covar + eps I)^{-1/2},
// computed via Newton-Schulz on the 3x3.
//
// R3: occupancy-driven redesign (R2 was reg-capped at 50% occ):
//  - Input staged in smem via cp.async.cg (no register-file transit).
//  - Each lane's copy set == its read set -> no barrier needed post-copy.
//  - Reduction + epilogue stream x from smem in 4-column chunks, keeping
//    live registers ~28; __launch_bounds__(256,8) -> 8 blocks/SM (100% occ).
//  - Newton-Schulz lane-parallel on warp 0 (lanes 0..7), 6 iterations.

#define NS_ITERS 6

__device__ __forceinline__ void cp_async16(unsigned saddr, const void* gptr) {
    asm volatile("cp.async.cg.shared.global [%0], [%1], 16;"
                 :: "r"(saddr), "l"(gptr));
}

__device__ __forceinline__ float sum4(float4 a) {
    return (a.x + a.y) + (a.z + a.w);
}
__device__ __forceinline__ float dot4(float4 a, float4 b, float acc) {
    acc = fmaf(a.x, b.x, acc);
    acc = fmaf(a.y, b.y, acc);
    acc = fmaf(a.z, b.z, acc);
    acc = fmaf(a.w, b.w, acc);
    return acc;
}

__global__ void __launch_bounds__(256, 8) eqln_kernel(
    const float* __restrict__ in,
    const float* __restrict__ weight,
    float* __restrict__ out,
    int nSamples)
{
    __shared__ float smx[8][768];      // staged input, sample per warp
    __shared__ float ssum[8][9];       // per-sample raw sums
    __shared__ float sres[8][9];       // per-sample S00..S22, b0,b1,b2

    const int warp = threadIdx.x >> 5;
    const int lane = threadIdx.x & 31;

    long sample = (long)blockIdx.x * 8 + warp;
    const bool valid = (sample < (long)nSamples);
    long ls = valid ? sample : (long)nSamples - 1;   // clamp for safe load

    // ---- stage this warp's sample into smem (bypasses RF) ----
    const char* gsrc = (const char*)(in + ls * 768);
    unsigned sbase = (unsigned)__cvta_generic_to_shared(&smx[warp][0]);
    #pragma unroll
    for (int c = 0; c < 6; c++) {
        int f4 = c * 32 + lane;                       // float4 idx 0..191
        cp_async16(sbase + f4 * 16, gsrc + (size_t)f4 * 16);
    }
    asm volatile("cp.async.commit_group;");
    asm volatile("cp.async.wait_group 0;" ::: "memory");
    // each lane reads only the float4s it copied itself -> no sync needed

    // ---- 9-quantity reduction (row sums + raw second moments) ----
    const float4* sx = (const float4*)&smx[warp][0];
    float s[9];
    #pragma unroll
    for (int q = 0; q < 9; q++) s[q] = 0.0f;

    #pragma unroll
    for (int c = 0; c < 2; c++) {
        float4 a = sx[       c * 32 + lane];
        float4 b = sx[ 64 +  c * 32 + lane];
        float4 d = sx[128 +  c * 32 + lane];
        s[0] += sum4(a);
        s[1] += sum4(b);
        s[2] += sum4(d);
        s[3] = dot4(a, a, s[3]);
        s[4] = dot4(a, b, s[4]);
        s[5] = dot4(a, d, s[5]);
        s[6] = dot4(b, b, s[6]);
        s[7] = dot4(b, d, s[7]);
        s[8] = dot4(d, d, s[8]);
    }

    #pragma unroll
    for (int q = 0; q < 9; q++) {
        #pragma unroll
        for (int o = 16; o > 0; o >>= 1)
            s[q] += __shfl_xor_sync(0xffffffffu, s[q], o);
    }
    if (lane == 0) {
        #pragma unroll
        for (int q = 0; q < 9; q++) ssum[warp][q] = s[q];
    }
    __syncthreads();

    // ---- lane-parallel Newton-Schulz: warp 0, lane k -> sample k ----
    if (warp == 0 && lane < 8) {
        float t[9];
        #pragma unroll
        for (int q = 0; q < 9; q++) t[q] = ssum[lane][q];

        const float invD = 1.0f / 256.0f;
        float m0 = t[0] * invD, m1 = t[1] * invD, m2 = t[2] * invD;

        // A = covar + EPS*diag(1,2,3) + EPS*I  (+EPS*I from 1/sqrt(s+eps))
        float a00 = fmaf(t[3], invD, -m0 * m0) + 2.0e-3f;
        float a01 = fmaf(t[4], invD, -m0 * m1);
        float a02 = fmaf(t[5], invD, -m0 * m2);
        float a11 = fmaf(t[6], invD, -m1 * m1) + 3.0e-3f;
        float a12 = fmaf(t[7], invD, -m1 * m2);
        float a22 = fmaf(t[8], invD, -m2 * m2) + 4.0e-3f;

        // Newton-Schulz for A^{-1/2}: B = A/c, X=I, X <- 0.5*X*(3I - B X^2)
        float c  = (a00 + a11 + a22) * (1.0f / 3.0f);
        float ic = 1.0f / c;
        float b00 = a00 * ic, b01 = a01 * ic, b02 = a02 * ic;
        float b11 = a11 * ic, b12 = a12 * ic, b22 = a22 * ic;

        float x00 = 1.0f, x01 = 0.0f, x02 = 0.0f;
        float x11 = 1.0f, x12 = 0.0f, x22 = 1.0f;

        #pragma unroll
        for (int it = 0; it < NS_ITERS; it++) {
            float t00 = x00*x00 + x01*x01 + x02*x02;
            float t01 = x00*x01 + x01*x11 + x02*x12;
            float t02 = x00*x02 + x01*x12 + x02*x22;
            float t11 = x01*x01 + x11*x11 + x12*x12;
            float t12 = x01*x02 + x11*x12 + x12*x22;
            float t22 = x02*x02 + x12*x12 + x22*x22;

            float w00 = b00*t00 + b01*t01 + b02*t02;
            float w01 = b00*t01 + b01*t11 + b02*t12;
            float w02 = b00*t02 + b01*t12 + b02*t22;
            float w11 = b01*t01 + b11*t11 + b12*t12;
            float w12 = b01*t02 + b11*t12 + b12*t22;
            float w22 = b02*t02 + b12*t12 + b22*t22;

            float q00 = 3.0f - w00, q01 = -w01, q02 = -w02;
            float q11 = 3.0f - w11, q12 = -w12, q22 = 3.0f - w22;

            float n00 = x00*q00 + x01*q01 + x02*q02;
            float n01 = x00*q01 + x01*q11 + x02*q12;
            float n02 = x00*q02 + x01*q12 + x02*q22;
            float n11 = x01*q01 + x11*q11 + x12*q12;
            float n12 = x01*q02 + x11*q12 + x12*q22;
            float n22 = x02*q02 + x12*q12 + x22*q22;

            x00 = 0.5f*n00; x01 = 0.5f*n01; x02 = 0.5f*n02;
            x11 = 0.5f*n11; x12 = 0.5f*n12; x22 = 0.5f*n22;
        }

        float isc = rsqrtf(c);   // A^{-1/2} = X / sqrt(c)
        float S00 = x00 * isc, S01 = x01 * isc, S02 = x02 * isc;
        float S11 = x11 * isc, S12 = x12 * isc, S22 = x22 * isc;

        sres[lane][0] = S00;
        sres[lane][1] = S01;
        sres[lane][2] = S02;
        sres[lane][3] = S11;
        sres[lane][4] = S12;
        sres[lane][5] = S22;
        // bias b = -S*m folds the mean subtraction into the transform
        sres[lane][6] = -(S00*m0 + S01*m1 + S02*m2);
        sres[lane][7] = -(S01*m0 + S11*m1 + S12*m2);
        sres[lane][8] = -(S02*m0 + S12*m1 + S22*m2);
    }
    __syncthreads();

    const float S00 = sres[warp][0], S01 = sres[warp][1], S02 = sres[warp][2];
    const float S11 = sres[warp][3], S12 = sres[warp][4], S22 = sres[warp][5];
    const float bb0 = sres[warp][6], bb1 = sres[warp][7], bb2 = sres[warp][8];

    // ---- epilogue: stream x back from smem, fused transform + weight ----
    if (valid) {
        const float4* __restrict__ w4p = (const float4*)weight;
        float4* __restrict__ xout = (float4*)(out + sample * 768);

        #pragma unroll
        for (int c = 0; c < 2; c++) {
            float4 a = sx[       c * 32 + lane];
            float4 b = sx[ 64 +  c * 32 + lane];
            float4 d = sx[128 +  c * 32 + lane];
            float4 w = w4p[c * 32 + lane];

            float4 o;
            o.x = fmaf(S00, a.x, fmaf(S01, b.x, fmaf(S02, d.x, bb0))) * w.x;
            o.y = fmaf(S00, a.y, fmaf(S01, b.y, fmaf(S02, d.y, bb0))) * w.y;
            o.z = fmaf(S00, a.z, fmaf(S01, b.z, fmaf(S02, d.z, bb0))) * w.z;
            o.w = fmaf(S00, a.w, fmaf(S01, b.w, fmaf(S02, d.w, bb0))) * w.w;
            xout[       c * 32 + lane] = o;

            o.x = fmaf(S01, a.x, fmaf(S11, b.x, fmaf(S12, d.x, bb1))) * w.x;
            o.y = fmaf(S01, a.y, fmaf(S11, b.y, fmaf(S12, d.y, bb1))) * w.y;
            o.z = fmaf(S01, a.z, fmaf(S11, b.z, fmaf(S12, d.z, bb1))) * w.z;
            o.w = fmaf(S01, a.w, fmaf(S11, b.w, fmaf(S12, d.w, bb1))) * w.w;
            xout[ 64 +  c * 32 + lane] = o;

            o.x = fmaf(S02, a.x, fmaf(S12, b.x, fmaf(S22, d.x, bb2))) * w.x;
            o.y = fmaf(S02, a.y, fmaf(S12, b.y, fmaf(S22, d.y, bb2))) * w.y;
            o.z = fmaf(S02, a.z, fmaf(S12, b.z, fmaf(S22, d.z, bb2))) * w.z;
            o.w = fmaf(S02, a.w, fmaf(S12, b.w, fmaf(S22, d.w, bb2))) * w.w;
            xout[128 +  c * 32 + lane] = o;
        }
    }
}

extern "C" void kernel_launch(void* const* d_in, const int* in_sizes, int n_in,
                              void* d_out, int out_size)
{
    const float* in = (const float*)d_in[0];
    const float* w  = (const float*)d_in[1];
    float* out      = (float*)d_out;

    int nSamples = in_sizes[0] / 768;        // N*3*256 elements -> N samples
    int grid = (nSamples + 7) / 8;
    eqln_kernel<<<grid, 256>>>(in, w, out, nSamples);
}

// round 4
// speedup vs baseline: 1.4092x; 1.0585x over previous
#include <cuda_runtime.h>
#include <cstdint>

// EquivariantLayerNorm: out = (covar + EPS*I)^{-1/2} @ (x - mean) * weight
// covar = xc @ xc^T / D + EPS*diag(1,2,3),  x: (N, 3, 256) fp32.
//
// (V diag(1/sqrt(s+eps)) V^T over SVD(covar)) == (covar + eps I)^{-1/2},
// computed via Newton-Schulz on the 3x3.
//
// R4: fully barrier-free. One warp per sample, end to end:
//   cp.async stage -> butterfly reduction (ALL lanes end with all 9 sums)
//   -> Newton-Schulz redundantly in every lane (no smem handoff, no bars)
//   -> fused epilogue with streaming stores.
// Warps are completely independent; no __syncthreads in the kernel.

#define NS_ITERS 5

__device__ __forceinline__ void cp_async16(unsigned saddr, const void* gptr) {
    asm volatile("cp.async.cg.shared.global [%0], [%1], 16;"
                 :: "r"(saddr), "l"(gptr));
}

__device__ __forceinline__ float sum4(float4 a) {
    return (a.x + a.y) + (a.z + a.w);
}
__device__ __forceinline__ float dot4(float4 a, float4 b, float acc) {
    acc = fmaf(a.x, b.x, acc);
    acc = fmaf(a.y, b.y, acc);
    acc = fmaf(a.z, b.z, acc);
    acc = fmaf(a.w, b.w, acc);
    return acc;
}

__global__ void __launch_bounds__(256, 6) eqln_kernel(
    const float* __restrict__ in,
    const float* __restrict__ weight,
    float* __restrict__ out,
    int nSamples)
{
    __shared__ float smx[8][768];      // staged input, one sample per warp

    const int warp = threadIdx.x >> 5;
    const int lane = threadIdx.x & 31;

    long sample = (long)blockIdx.x * 8 + warp;
    const bool valid = (sample < (long)nSamples);
    long ls = valid ? sample : (long)nSamples - 1;   // clamp for safe load

    // ---- stage this warp's sample into smem (bypasses RF, L2-only path) ----
    const char* gsrc = (const char*)(in + ls * 768);
    unsigned sbase = (unsigned)__cvta_generic_to_shared(&smx[warp][0]);
    #pragma unroll
    for (int c = 0; c < 6; c++) {
        int f4 = c * 32 + lane;                       // float4 idx 0..191
        cp_async16(sbase + f4 * 16, gsrc + (size_t)f4 * 16);
    }
    asm volatile("cp.async.commit_group;");
    asm volatile("cp.async.wait_group 0;" ::: "memory");
    // each lane only ever reads the float4s it copied itself -> no sync needed

    // ---- 9-quantity reduction (row sums + raw second moments) ----
    const float4* sx = (const float4*)&smx[warp][0];
    float s[9];
    #pragma unroll
    for (int q = 0; q < 9; q++) s[q] = 0.0f;

    #pragma unroll
    for (int c = 0; c < 2; c++) {
        float4 a = sx[       c * 32 + lane];
        float4 b = sx[ 64 +  c * 32 + lane];
        float4 d = sx[128 +  c * 32 + lane];
        s[0] += sum4(a);
        s[1] += sum4(b);
        s[2] += sum4(d);
        s[3] = dot4(a, a, s[3]);
        s[4] = dot4(a, b, s[4]);
        s[5] = dot4(a, d, s[5]);
        s[6] = dot4(b, b, s[6]);
        s[7] = dot4(b, d, s[7]);
        s[8] = dot4(d, d, s[8]);
    }

    // butterfly: every lane ends with the full sums
    #pragma unroll
    for (int q = 0; q < 9; q++) {
        #pragma unroll
        for (int o = 16; o > 0; o >>= 1)
            s[q] += __shfl_xor_sync(0xffffffffu, s[q], o);
    }

    // ---- Newton-Schulz, redundant in every lane (no handoff, no barriers) ----
    const float invD = 1.0f / 256.0f;
    const float m0 = s[0] * invD, m1 = s[1] * invD, m2 = s[2] * invD;

    // A = covar + EPS*diag(1,2,3) + EPS*I   (the +EPS*I from 1/sqrt(s+eps))
    float a00 = fmaf(s[3], invD, -m0 * m0) + 2.0e-3f;
    float a01 = fmaf(s[4], invD, -m0 * m1);
    float a02 = fmaf(s[5], invD, -m0 * m2);
    float a11 = fmaf(s[6], invD, -m1 * m1) + 3.0e-3f;
    float a12 = fmaf(s[7], invD, -m1 * m2);
    float a22 = fmaf(s[8], invD, -m2 * m2) + 4.0e-3f;

    // B = A/c, X = I, X <- 0.5*X*(3I - B X^2);  A^{-1/2} = X / sqrt(c)
    float c  = (a00 + a11 + a22) * (1.0f / 3.0f);
    float ic = 1.0f / c;
    float b00 = a00 * ic, b01 = a01 * ic, b02 = a02 * ic;
    float b11 = a11 * ic, b12 = a12 * ic, b22 = a22 * ic;

    float x00 = 1.0f, x01 = 0.0f, x02 = 0.0f;
    float x11 = 1.0f, x12 = 0.0f, x22 = 1.0f;

    #pragma unroll
    for (int it = 0; it < NS_ITERS; it++) {
        float t00 = x00*x00 + x01*x01 + x02*x02;
        float t01 = x00*x01 + x01*x11 + x02*x12;
        float t02 = x00*x02 + x01*x12 + x02*x22;
        float t11 = x01*x01 + x11*x11 + x12*x12;
        float t12 = x01*x02 + x11*x12 + x12*x22;
        float t22 = x02*x02 + x12*x12 + x22*x22;

        float w00 = b00*t00 + b01*t01 + b02*t02;
        float w01 = b00*t01 + b01*t11 + b02*t12;
        float w02 = b00*t02 + b01*t12 + b02*t22;
        float w11 = b01*t01 + b11*t11 + b12*t12;
        float w12 = b01*t02 + b11*t12 + b12*t22;
        float w22 = b02*t02 + b12*t12 + b22*t22;

        float q00 = 3.0f - w00, q01 = -w01, q02 = -w02;
        float q11 = 3.0f - w11, q12 = -w12, q22 = 3.0f - w22;

        float n00 = x00*q00 + x01*q01 + x02*q02;
        float n01 = x00*q01 + x01*q11 + x02*q12;
        float n02 = x00*q02 + x01*q12 + x02*q22;
        float n11 = x01*q01 + x11*q11 + x12*q12;
        float n12 = x01*q02 + x11*q12 + x12*q22;
        float n22 = x02*q02 + x12*q12 + x22*q22;

        x00 = 0.5f*n00; x01 = 0.5f*n01; x02 = 0.5f*n02;
        x11 = 0.5f*n11; x12 = 0.5f*n12; x22 = 0.5f*n22;
    }

    const float isc = rsqrtf(c);
    const float S00 = x00 * isc, S01 = x01 * isc, S02 = x02 * isc;
    const float S11 = x11 * isc, S12 = x12 * isc, S22 = x22 * isc;
    // bias b = -S*m folds the mean subtraction into the transform
    const float bb0 = -(S00*m0 + S01*m1 + S02*m2);
    const float bb1 = -(S01*m0 + S11*m1 + S12*m2);
    const float bb2 = -(S02*m0 + S12*m1 + S22*m2);

    // ---- epilogue: stream x back from smem, fused transform + weight ----
    if (valid) {
        const float4* __restrict__ w4p = (const float4*)weight;
        float4* __restrict__ xout = (float4*)(out + sample * 768);

        #pragma unroll
        for (int c2 = 0; c2 < 2; c2++) {
            float4 a = sx[       c2 * 32 + lane];
            float4 b = sx[ 64 +  c2 * 32 + lane];
            float4 d = sx[128 +  c2 * 32 + lane];
            float4 w = w4p[c2 * 32 + lane];

            float4 o;
            o.x = fmaf(S00, a.x, fmaf(S01, b.x, fmaf(S02, d.x, bb0))) * w.x;
            o.y = fmaf(S00, a.y, fmaf(S01, b.y, fmaf(S02, d.y, bb0))) * w.y;
            o.z = fmaf(S00, a.z, fmaf(S01, b.z, fmaf(S02, d.z, bb0))) * w.z;
            o.w = fmaf(S00, a.w, fmaf(S01, b.w, fmaf(S02, d.w, bb0))) * w.w;
            __stcs(&xout[       c2 * 32 + lane], o);

            o.x = fmaf(S01, a.x, fmaf(S11, b.x, fmaf(S12, d.x, bb1))) * w.x;
            o.y = fmaf(S01, a.y, fmaf(S11, b.y, fmaf(S12, d.y, bb1))) * w.y;
            o.z = fmaf(S01, a.z, fmaf(S11, b.z, fmaf(S12, d.z, bb1))) * w.z;
            o.w = fmaf(S01, a.w, fmaf(S11, b.w, fmaf(S12, d.w, bb1))) * w.w;
            __stcs(&xout[ 64 +  c2 * 32 + lane], o);

            o.x = fmaf(S02, a.x, fmaf(S12, b.x, fmaf(S22, d.x, bb2))) * w.x;
            o.y = fmaf(S02, a.y, fmaf(S12, b.y, fmaf(S22, d.y, bb2))) * w.y;
            o.z = fmaf(S02, a.z, fmaf(S12, b.z, fmaf(S22, d.z, bb2))) * w.z;
            o.w = fmaf(S02, a.w, fmaf(S12, b.w, fmaf(S22, d.w, bb2))) * w.w;
            __stcs(&xout[128 +  c2 * 32 + lane], o);
        }
    }
}

extern "C" void kernel_launch(void* const* d_in, const int* in_sizes, int n_in,
                              void* d_out, int out_size)
{
    const float* in = (const float*)d_in[0];
    const float* w  = (const float*)d_in[1];
    float* out      = (float*)d_out;

    int nSamples = in_sizes[0] / 768;        // N*3*256 elements -> N samples
    int grid = (nSamples + 7) / 8;
    eqln_kernel<<<grid, 256>>>(in, w, out, nSamples);
}